// round 6
// baseline (speedup 1.0000x reference)
#include <cuda_runtime.h>

#define B_  16
#define T_  128
#define H_  1024
#define FH  4096
#define V_  32000
#define M_  2048   // B_*T_

// ---------------- device scratch (allocation-free) ----------------
__device__ float g_Pre[M_ * FH];   // 32 MB: X@Wx2^T + b2, rows m = t*16+b
__device__ float g_Hs [M_ * H_];   //  8 MB: emitted h, rows m = t*16+b
__device__ float g_At [B_ * FH];   // tanh(pre-activations) of current step
__device__ float g_c  [B_ * H_];   // cell state,   [b][k]
__device__ float g_h  [B_ * H_];   // hidden state, [b][k]

__device__ __forceinline__ float sigf(float x) { return 1.f / (1.f + __expf(-x)); }

// =====================================================================
// Tiled 128x128x16 SGEMM, C = A @ B^T + bias. 256 threads, 8x8 microtile.
//  GATHER : A row m is W_emb[idx[b*T_+t]] (m = t*16+b); writes g_Pre.
//  SOFTMAX: A = g_Hs; epilogue does softmax over each 16-row (batch) group
//           and writes out[b][t][v].
// =====================================================================
template<bool GATHER, bool SOFTMAX>
__global__ __launch_bounds__(256, 2)
void sgemm(const float* __restrict__ A, const float* __restrict__ Bw,
           const float* __restrict__ bias, const int* __restrict__ idx,
           float* __restrict__ C)
{
    __shared__ float As[16][132];
    __shared__ float Bs[16][132];

    const int tid = threadIdx.x;
    const int ty  = tid >> 4, tx = tid & 15;
    const int m0  = blockIdx.x * 128;
    const int n0  = blockIdx.y * 128;

    // load-role: row r, quad lq (+2 per pass)
    const int r  = tid >> 1;
    const int lq = tid & 1;

    const float* arow;
    if (GATHER) {
        int m = m0 + r;
        int t = m >> 4, b = m & 15;
        arow = A + (size_t)idx[b * T_ + t] * H_;
    } else {
        arow = g_Hs + (size_t)(m0 + r) * H_;
    }
    const float* brow = Bw + (size_t)(n0 + r) * H_;

    float acc[8][8];
#pragma unroll
    for (int i = 0; i < 8; i++)
#pragma unroll
        for (int j = 0; j < 8; j++) acc[i][j] = 0.f;

    for (int k0 = 0; k0 < H_; k0 += 16) {
#pragma unroll
        for (int p = 0; p < 2; p++) {
            int q = lq + 2 * p;  // 0..3
            float4 a4 = *reinterpret_cast<const float4*>(arow + k0 + q * 4);
            float4 b4 = *reinterpret_cast<const float4*>(brow + k0 + q * 4);
            As[q*4+0][r] = a4.x; As[q*4+1][r] = a4.y;
            As[q*4+2][r] = a4.z; As[q*4+3][r] = a4.w;
            Bs[q*4+0][r] = b4.x; Bs[q*4+1][r] = b4.y;
            Bs[q*4+2][r] = b4.z; Bs[q*4+3][r] = b4.w;
        }
        __syncthreads();
#pragma unroll
        for (int kk = 0; kk < 16; kk++) {
            float a[8], b[8];
            *reinterpret_cast<float4*>(&a[0]) = *reinterpret_cast<float4*>(&As[kk][ty*8]);
            *reinterpret_cast<float4*>(&a[4]) = *reinterpret_cast<float4*>(&As[kk][ty*8+4]);
            *reinterpret_cast<float4*>(&b[0]) = *reinterpret_cast<float4*>(&Bs[kk][tx*8]);
            *reinterpret_cast<float4*>(&b[4]) = *reinterpret_cast<float4*>(&Bs[kk][tx*8+4]);
#pragma unroll
            for (int i = 0; i < 8; i++)
#pragma unroll
                for (int j = 0; j < 8; j++)
                    acc[i][j] = fmaf(a[i], b[j], acc[i][j]);
        }
        __syncthreads();
    }

    float bs[8];
#pragma unroll
    for (int j = 0; j < 8; j++) bs[j] = bias[n0 + tx * 8 + j];

    if (!SOFTMAX) {
        // write Pre rows
#pragma unroll
        for (int i = 0; i < 8; i++) {
            float* crow = g_Pre + (size_t)(m0 + ty * 8 + i) * FH + n0 + tx * 8;
            float4 o0, o1;
            o0.x = acc[i][0]+bs[0]; o0.y = acc[i][1]+bs[1];
            o0.z = acc[i][2]+bs[2]; o0.w = acc[i][3]+bs[3];
            o1.x = acc[i][4]+bs[4]; o1.y = acc[i][5]+bs[5];
            o1.z = acc[i][6]+bs[6]; o1.w = acc[i][7]+bs[7];
            *reinterpret_cast<float4*>(crow)     = o0;
            *reinterpret_cast<float4*>(crow + 4) = o1;
        }
    } else {
        // add bias, softmax over the 16-row batch group (one group per warp)
#pragma unroll
        for (int i = 0; i < 8; i++)
#pragma unroll
            for (int j = 0; j < 8; j++) acc[i][j] += bs[j];
#pragma unroll
        for (int j = 0; j < 8; j++) {
            float mx = acc[0][j];
#pragma unroll
            for (int i = 1; i < 8; i++) mx = fmaxf(mx, acc[i][j]);
            mx = fmaxf(mx, __shfl_xor_sync(0xffffffffu, mx, 16));
            float s = 0.f;
#pragma unroll
            for (int i = 0; i < 8; i++) { acc[i][j] = __expf(acc[i][j] - mx); s += acc[i][j]; }
            s += __shfl_xor_sync(0xffffffffu, s, 16);
            float inv = 1.f / s;
#pragma unroll
            for (int i = 0; i < 8; i++) acc[i][j] *= inv;
        }
        const int tcol = (m0 >> 4) + (tid >> 5);   // t, constant per warp
#pragma unroll
        for (int i = 0; i < 8; i++) {
            int b = ((ty & 1) << 3) + i;
            float* orow = C + (size_t)b * (T_ * (size_t)V_) + (size_t)tcol * V_ + n0 + tx * 8;
            float4 o0, o1;
            o0.x = acc[i][0]; o0.y = acc[i][1]; o0.z = acc[i][2]; o0.w = acc[i][3];
            o1.x = acc[i][4]; o1.y = acc[i][5]; o1.z = acc[i][6]; o1.w = acc[i][7];
            *reinterpret_cast<float4*>(orow)     = o0;
            *reinterpret_cast<float4*>(orow + 4) = o1;
        }
    }
}

// =====================================================================
// LSTM step GEMM: At[b][n] = tanh( Pre[t*16+b][n] + sum_k h[b][k]*Wh[n][k] )
// grid 128 blocks x 256 threads; warp handles 4 n, lanes span K.
// =====================================================================
__global__ __launch_bounds__(256, 1)
void lstm_gemm(const float* __restrict__ Wh, int t)
{
    __shared__ float hs[16][512];
    const int tid = threadIdx.x;
    const int w   = tid >> 5, l = tid & 31;
    const int nb  = blockIdx.x * 32 + w * 4;
    const float* pre = g_Pre + (size_t)(t * 16) * FH;

    float acc[4][16];
#pragma unroll
    for (int j = 0; j < 4; j++)
#pragma unroll
        for (int b = 0; b < 16; b++) acc[j][b] = 0.f;

    for (int half = 0; half < 2; half++) {
        // stage h[b][half*512 .. +512) -> hs
#pragma unroll
        for (int p = 0; p < 8; p++) {
            int e  = p * 256 + tid;     // float4 index, 0..2047
            int b  = e >> 7;
            int c4 = e & 127;
            *reinterpret_cast<float4*>(&hs[b][c4 * 4]) =
                *reinterpret_cast<const float4*>(g_h + b * H_ + half * 512 + c4 * 4);
        }
        __syncthreads();
#pragma unroll
        for (int it = 0; it < 4; it++) {
            int kl = it * 128 + l * 4;
            int k  = half * 512 + kl;
            float4 w4[4];
#pragma unroll
            for (int j = 0; j < 4; j++)
                w4[j] = *reinterpret_cast<const float4*>(Wh + (size_t)(nb + j) * H_ + k);
#pragma unroll
            for (int b = 0; b < 16; b++) {
                float4 h4 = *reinterpret_cast<const float4*>(&hs[b][kl]);
#pragma unroll
                for (int j = 0; j < 4; j++) {
                    acc[j][b] = fmaf(w4[j].x, h4.x, acc[j][b]);
                    acc[j][b] = fmaf(w4[j].y, h4.y, acc[j][b]);
                    acc[j][b] = fmaf(w4[j].z, h4.z, acc[j][b]);
                    acc[j][b] = fmaf(w4[j].w, h4.w, acc[j][b]);
                }
            }
        }
        __syncthreads();
    }

    // cross-lane reduce (lanes hold disjoint K partials)
#pragma unroll
    for (int j = 0; j < 4; j++)
#pragma unroll
        for (int b = 0; b < 16; b++) {
#pragma unroll
            for (int d = 16; d >= 1; d >>= 1)
                acc[j][b] += __shfl_xor_sync(0xffffffffu, acc[j][b], d);
        }

    if (l < 16) {
#pragma unroll
        for (int j = 0; j < 4; j++) {
            int n = nb + j;
            g_At[l * FH + n] = tanhf(acc[j][l] + pre[(size_t)l * FH + n]);
        }
    }
}

// =====================================================================
// LSTM gate/state update. Quirks preserved:
//   gates = {sig,tanh,sig,sig} of tanh'ed pre-activations (A = tanh(...))
//   h_next = o * tanh(c_OLD); emitted hs[t] = h BEFORE update.
// Writes Hs[t+1] = h_next (Hs[0] zeroed by init).
// =====================================================================
__global__ void lstm_update(int t)
{
    int e = blockIdx.x * blockDim.x + threadIdx.x;   // 0..16383
    int b = e >> 10, j = e & 1023;
    const float* Ab = g_At + b * FH;
    float f = sigf (Ab[j]);
    float g = tanhf(Ab[1024 + j]);
    float i = sigf (Ab[2048 + j]);
    float o = sigf (Ab[3072 + j]);
    float cold = g_c[e];
    g_c[e] = f * cold + g * i;
    float hn = o * tanhf(cold);
    g_h[e] = hn;
    g_Hs[(size_t)(t + 1) * (B_ * H_) + e] = hn;
}

__global__ void lstm_init()
{
    int e = blockIdx.x * blockDim.x + threadIdx.x;
    if (e < B_ * H_) { g_c[e] = 0.f; g_h[e] = 0.f; g_Hs[e] = 0.f; }
}

// =====================================================================
extern "C" void kernel_launch(void* const* d_in, const int* in_sizes, int n_in,
                              void* d_out, int out_size)
{
    const int*   idx   = (const int*)  d_in[0];
    const float* W_emb = (const float*)d_in[1];
    const float* Wx2   = (const float*)d_in[2];
    const float* Wh2   = (const float*)d_in[3];
    const float* b2    = (const float*)d_in[4];
    const float* Wa    = (const float*)d_in[5];
    const float* ba    = (const float*)d_in[6];
    float* out = (float*)d_out;
    (void)in_sizes; (void)n_in; (void)out_size;

    lstm_init<<<64, 256>>>();

    // Pre = gather(W_emb, idx) @ Wx2^T + b2   (rows m = t*16+b)
    sgemm<true, false><<<dim3(16, FH / 128), 256>>>(W_emb, Wx2, b2, idx, out);

    // 127 recurrent steps (step 127's update is never consumed -> skipped)
    for (int t = 0; t < T_ - 1; t++) {
        lstm_gemm<<<128, 256>>>(Wh2, t);
        lstm_update<<<64, 256>>>(t);
    }

    // V = Hs @ Wa^T + ba, fused softmax over batch axis -> out[b][t][v]
    sgemm<false, true><<<dim3(16, V_ / 128), 256>>>(W_emb, Wa, ba, idx, out);
}

// round 7
// speedup vs baseline: 1.0961x; 1.0961x over previous
#include <cuda_runtime.h>

#define B_  16
#define T_  128
#define H_  1024
#define FH  4096
#define V_  32000
#define M_  2048   // B_*T_

// ---------------- device scratch (allocation-free) ----------------
__device__ float g_Pre[M_ * FH];   // 32 MB: X@Wx2^T + b2, rows m = t*16+b
__device__ float g_Hs [M_ * H_];   //  8 MB: emitted h, rows m = t*16+b
__device__ float g_c  [B_ * H_];   // cell state,   [b][k]
__device__ float g_h  [B_ * H_];   // hidden state, [b][k]

__device__ __forceinline__ float sigf(float x) { return 1.f / (1.f + __expf(-x)); }

// ---------------- packed fp32x2 helpers (sm_100+) ----------------
__device__ __forceinline__ unsigned long long pack2(float x, float y) {
    unsigned long long r;
    asm("mov.b64 %0, {%1, %2};" : "=l"(r) : "f"(x), "f"(y));
    return r;
}
__device__ __forceinline__ void fma2(unsigned long long& d,
                                     unsigned long long a, unsigned long long b) {
    asm("fma.rn.f32x2 %0, %1, %2, %0;" : "+l"(d) : "l"(a), "l"(b));
}
__device__ __forceinline__ float2 unpk(unsigned long long v) {
    float2 r;
    asm("mov.b64 {%0, %1}, %2;" : "=f"(r.x), "=f"(r.y) : "l"(v));
    return r;
}

// =====================================================================
// Tiled 128x128x16 SGEMM, C = A @ B^T + bias. 256 threads, 8x8 microtile,
// packed f32x2 inner product (2 FMA per fma-pipe slot).
//  GATHER : A row m is W_emb[idx[b*T_+t]] (m = t*16+b); writes g_Pre.
//  SOFTMAX: A = g_Hs; epilogue softmaxes each 16-row batch group (one
//           group per warp) and writes out[b][t][v].
// =====================================================================
template<bool GATHER, bool SOFTMAX>
__global__ __launch_bounds__(256, 2)
void sgemm(const float* __restrict__ A, const float* __restrict__ Bw,
           const float* __restrict__ bias, const int* __restrict__ idx,
           float* __restrict__ C)
{
    __shared__ alignas(16) float As[16][132];
    __shared__ alignas(16) float Bs[16][132];

    const int tid = threadIdx.x;
    const int ty  = tid >> 4, tx = tid & 15;
    const int m0  = blockIdx.x * 128;
    const int n0  = blockIdx.y * 128;

    const int r  = tid >> 1;     // load-role row
    const int lq = tid & 1;

    const float* arow;
    if (GATHER) {
        int m = m0 + r;
        int t = m >> 4, b = m & 15;
        arow = A + (size_t)idx[b * T_ + t] * H_;
    } else {
        arow = g_Hs + (size_t)(m0 + r) * H_;
    }
    const float* brow = Bw + (size_t)(n0 + r) * H_;

    unsigned long long acc2[8][4];
#pragma unroll
    for (int i = 0; i < 8; i++)
#pragma unroll
        for (int j = 0; j < 4; j++) acc2[i][j] = 0ull;

    for (int k0 = 0; k0 < H_; k0 += 16) {
#pragma unroll
        for (int p = 0; p < 2; p++) {
            int q = lq + 2 * p;  // 0..3
            float4 a4 = *reinterpret_cast<const float4*>(arow + k0 + q * 4);
            float4 b4 = *reinterpret_cast<const float4*>(brow + k0 + q * 4);
            As[q*4+0][r] = a4.x; As[q*4+1][r] = a4.y;
            As[q*4+2][r] = a4.z; As[q*4+3][r] = a4.w;
            Bs[q*4+0][r] = b4.x; Bs[q*4+1][r] = b4.y;
            Bs[q*4+2][r] = b4.z; Bs[q*4+3][r] = b4.w;
        }
        __syncthreads();
#pragma unroll
        for (int kk = 0; kk < 16; kk++) {
            float a[8];
            *reinterpret_cast<float4*>(&a[0]) = *reinterpret_cast<float4*>(&As[kk][ty*8]);
            *reinterpret_cast<float4*>(&a[4]) = *reinterpret_cast<float4*>(&As[kk][ty*8+4]);
            ulonglong2 u0 = *reinterpret_cast<ulonglong2*>(&Bs[kk][tx*8]);
            ulonglong2 u1 = *reinterpret_cast<ulonglong2*>(&Bs[kk][tx*8+4]);
            unsigned long long bp[4] = {u0.x, u0.y, u1.x, u1.y};
#pragma unroll
            for (int i = 0; i < 8; i++) {
                unsigned long long ap = pack2(a[i], a[i]);
#pragma unroll
                for (int j = 0; j < 4; j++) fma2(acc2[i][j], ap, bp[j]);
            }
        }
        __syncthreads();
    }

    // unpack to scalar accumulators
    float acc[8][8];
#pragma unroll
    for (int i = 0; i < 8; i++)
#pragma unroll
        for (int j = 0; j < 4; j++) {
            float2 p = unpk(acc2[i][j]);
            acc[i][2*j] = p.x; acc[i][2*j+1] = p.y;
        }

    float bs[8];
#pragma unroll
    for (int j = 0; j < 8; j++) bs[j] = bias[n0 + tx * 8 + j];

    if (!SOFTMAX) {
#pragma unroll
        for (int i = 0; i < 8; i++) {
            float* crow = g_Pre + (size_t)(m0 + ty * 8 + i) * FH + n0 + tx * 8;
            float4 o0, o1;
            o0.x = acc[i][0]+bs[0]; o0.y = acc[i][1]+bs[1];
            o0.z = acc[i][2]+bs[2]; o0.w = acc[i][3]+bs[3];
            o1.x = acc[i][4]+bs[4]; o1.y = acc[i][5]+bs[5];
            o1.z = acc[i][6]+bs[6]; o1.w = acc[i][7]+bs[7];
            *reinterpret_cast<float4*>(crow)     = o0;
            *reinterpret_cast<float4*>(crow + 4) = o1;
        }
    } else {
#pragma unroll
        for (int i = 0; i < 8; i++)
#pragma unroll
            for (int j = 0; j < 8; j++) acc[i][j] += bs[j];
#pragma unroll
        for (int j = 0; j < 8; j++) {
            float mx = acc[0][j];
#pragma unroll
            for (int i = 1; i < 8; i++) mx = fmaxf(mx, acc[i][j]);
            mx = fmaxf(mx, __shfl_xor_sync(0xffffffffu, mx, 16));
            float s = 0.f;
#pragma unroll
            for (int i = 0; i < 8; i++) { acc[i][j] = __expf(acc[i][j] - mx); s += acc[i][j]; }
            s += __shfl_xor_sync(0xffffffffu, s, 16);
            float inv = 1.f / s;
#pragma unroll
            for (int i = 0; i < 8; i++) acc[i][j] *= inv;
        }
        const int tcol = (m0 >> 4) + (tid >> 5);   // t, constant per warp
#pragma unroll
        for (int i = 0; i < 8; i++) {
            int b = ((ty & 1) << 3) + i;
            float* orow = C + (size_t)b * (T_ * (size_t)V_) + (size_t)tcol * V_ + n0 + tx * 8;
            float4 o0, o1;
            o0.x = acc[i][0]; o0.y = acc[i][1]; o0.z = acc[i][2]; o0.w = acc[i][3];
            o1.x = acc[i][4]; o1.y = acc[i][5]; o1.z = acc[i][6]; o1.w = acc[i][7];
            *reinterpret_cast<float4*>(orow)     = o0;
            *reinterpret_cast<float4*>(orow + 4) = o1;
        }
    }
}

// =====================================================================
// Fused LSTM step: recurrent GEMM + gate nonlinearities + state update.
// 128 blocks x 256 threads. Warp w of block handles hidden index
// j = blockIdx.x*8 + w, computing all 4 gate rows {j,1024+j,2048+j,3072+j}.
// Lanes span K with packed f32x2 accumulation; butterfly reduce; lanes
// 0..15 (= batch) apply the faithful-quirk update:
//   A = tanh(pre);  f,i,o = sig(A.), g = tanh(A.)
//   c_new = f*c_old + g*i;  h_next = o*tanh(c_OLD);  Hs[t+1] = h_next.
// =====================================================================
__global__ __launch_bounds__(256, 1)
void lstm_step(const float* __restrict__ Wh, int t)
{
    __shared__ alignas(16) float hs[16][512];
    const int tid = threadIdx.x;
    const int w   = tid >> 5, l = tid & 31;
    const int j   = blockIdx.x * 8 + w;

    unsigned long long acc2[4][16];
#pragma unroll
    for (int g = 0; g < 4; g++)
#pragma unroll
        for (int b = 0; b < 16; b++) acc2[g][b] = 0ull;

    for (int half = 0; half < 2; half++) {
#pragma unroll
        for (int p = 0; p < 8; p++) {
            int e  = p * 256 + tid;     // float4 index, 0..2047
            int b  = e >> 7;
            int c4 = e & 127;
            *reinterpret_cast<float4*>(&hs[b][c4 * 4]) =
                *reinterpret_cast<const float4*>(g_h + b * H_ + half * 512 + c4 * 4);
        }
        __syncthreads();
#pragma unroll
        for (int it = 0; it < 4; it++) {
            int kl = it * 128 + l * 4;
            int k  = half * 512 + kl;
            unsigned long long wp[4][2];
#pragma unroll
            for (int g = 0; g < 4; g++) {
                float4 w4 = *reinterpret_cast<const float4*>(
                    Wh + (size_t)(g * 1024 + j) * H_ + k);
                wp[g][0] = pack2(w4.x, w4.y);
                wp[g][1] = pack2(w4.z, w4.w);
            }
#pragma unroll
            for (int b = 0; b < 16; b++) {
                float4 h4 = *reinterpret_cast<float4*>(&hs[b][kl]);
                unsigned long long hp0 = pack2(h4.x, h4.y);
                unsigned long long hp1 = pack2(h4.z, h4.w);
#pragma unroll
                for (int g = 0; g < 4; g++) {
                    fma2(acc2[g][b], wp[g][0], hp0);
                    fma2(acc2[g][b], wp[g][1], hp1);
                }
            }
        }
        __syncthreads();
    }

    // cross-lane reduce (lanes hold disjoint K partials)
    float r[4][16];
#pragma unroll
    for (int g = 0; g < 4; g++)
#pragma unroll
        for (int b = 0; b < 16; b++) {
            float2 p = unpk(acc2[g][b]);
            float s = p.x + p.y;
#pragma unroll
            for (int d = 16; d >= 1; d >>= 1)
                s += __shfl_xor_sync(0xffffffffu, s, d);
            r[g][b] = s;
        }

    if (l < 16) {
        const int b = l;
        const float* pre = g_Pre + (size_t)(t * 16 + b) * FH;
        float Af = tanhf(r[0][b] + pre[j]);
        float Ag = tanhf(r[1][b] + pre[1024 + j]);
        float Ai = tanhf(r[2][b] + pre[2048 + j]);
        float Ao = tanhf(r[3][b] + pre[3072 + j]);
        float f  = sigf(Af);
        float gg = tanhf(Ag);
        float ii = sigf(Ai);
        float oo = sigf(Ao);
        int e = b * H_ + j;
        float cold = g_c[e];
        g_c[e] = f * cold + gg * ii;
        float hn = oo * tanhf(cold);
        g_h[e] = hn;
        g_Hs[(size_t)(t + 1) * (B_ * H_) + e] = hn;
    }
}

__global__ void lstm_init()
{
    int e = blockIdx.x * blockDim.x + threadIdx.x;
    if (e < B_ * H_) { g_c[e] = 0.f; g_h[e] = 0.f; g_Hs[e] = 0.f; }
}

// =====================================================================
extern "C" void kernel_launch(void* const* d_in, const int* in_sizes, int n_in,
                              void* d_out, int out_size)
{
    const int*   idx   = (const int*)  d_in[0];
    const float* W_emb = (const float*)d_in[1];
    const float* Wx2   = (const float*)d_in[2];
    const float* Wh2   = (const float*)d_in[3];
    const float* b2    = (const float*)d_in[4];
    const float* Wa    = (const float*)d_in[5];
    const float* ba    = (const float*)d_in[6];
    float* out = (float*)d_out;
    (void)in_sizes; (void)n_in; (void)out_size;

    lstm_init<<<64, 256>>>();

    // Pre = gather(W_emb, idx) @ Wx2^T + b2   (rows m = t*16+b)
    sgemm<true, false><<<dim3(16, FH / 128), 256>>>(W_emb, Wx2, b2, idx, out);

    // 127 fused recurrent steps (step 127's update is never consumed)
    for (int t = 0; t < T_ - 1; t++)
        lstm_step<<<128, 256>>>(Wh2, t);

    // V = Hs @ Wa^T + ba, fused softmax over batch axis -> out[b][t][v]
    sgemm<false, true><<<dim3(16, V_ / 128), 256>>>(W_emb, Wa, ba, idx, out);
}